// round 15
// baseline (speedup 1.0000x reference)
#include <cuda_runtime.h>
#include <math.h>

#define EPSF 1e-7f

static constexpr int B = 16, H = 224, W = 224, C = 32;
static constexpr int TW = 16;       // output columns per block
static constexpr int CH = 112;      // output rows per block
static constexpr int NCHUNK = 14;   // float2 row-chunks (28 rows of ring)
static constexpr int CHUNK2 = 1024; // float2 per chunk: 32 l x 32 c
static constexpr int QBYTES = NCHUNK * CHUNK2 * 8;  // 114688 B -> 2 CTAs/SM
static constexpr int NSUP = (CH + 16) / 4;          // 32 super-iterations

// Static init; atomicMin/Max accumulation is idempotent across graph replays.
__device__ unsigned g_mn[B] = {
    0xFFFFFFFFu, 0xFFFFFFFFu, 0xFFFFFFFFu, 0xFFFFFFFFu,
    0xFFFFFFFFu, 0xFFFFFFFFu, 0xFFFFFFFFu, 0xFFFFFFFFu,
    0xFFFFFFFFu, 0xFFFFFFFFu, 0xFFFFFFFFu, 0xFFFFFFFFu,
    0xFFFFFFFFu, 0xFFFFFFFFu, 0xFFFFFFFFu, 0xFFFFFFFFu};
__device__ unsigned g_mx[B] = {0};

__device__ __forceinline__ unsigned fenc(float f) {
    unsigned u = __float_as_uint(f);
    return (u & 0x80000000u) ? ~u : (u | 0x80000000u);
}
__device__ __forceinline__ float fdec(unsigned u) {
    return __uint_as_float((u & 0x80000000u) ? (u ^ 0x80000000u) : ~u);
}

// K1: per-sample min/max. grid = (56, B), 256 threads, 4 accumulators (MLP=4).
__global__ void __launch_bounds__(256) k1_minmax(const float4* __restrict__ x) {
    int b = blockIdx.y;
    const int N4 = H * W * C / 4;
    const int S  = 56 * 256;
    const float4* xb = x + (size_t)b * N4;
    int tid = blockIdx.x * 256 + threadIdx.x;
    float mn0 = INFINITY, mn1 = INFINITY, mn2 = INFINITY, mn3 = INFINITY;
    float mx0 = -INFINITY, mx1 = -INFINITY, mx2 = -INFINITY, mx3 = -INFINITY;
    #pragma unroll 1
    for (int i = tid; i < N4; i += 4 * S) {
        float4 a  = xb[i];
        float4 b4 = xb[i + S];
        float4 c4 = xb[i + 2 * S];
        float4 d4 = xb[i + 3 * S];
        mn0 = fminf(mn0, fminf(fminf(a.x, a.y), fminf(a.z, a.w)));
        mx0 = fmaxf(mx0, fmaxf(fmaxf(a.x, a.y), fmaxf(a.z, a.w)));
        mn1 = fminf(mn1, fminf(fminf(b4.x, b4.y), fminf(b4.z, b4.w)));
        mx1 = fmaxf(mx1, fmaxf(fmaxf(b4.x, b4.y), fmaxf(b4.z, b4.w)));
        mn2 = fminf(mn2, fminf(fminf(c4.x, c4.y), fminf(c4.z, c4.w)));
        mx2 = fmaxf(mx2, fmaxf(fmaxf(c4.x, c4.y), fmaxf(c4.z, c4.w)));
        mn3 = fminf(mn3, fminf(fminf(d4.x, d4.y), fminf(d4.z, d4.w)));
        mx3 = fmaxf(mx3, fmaxf(fmaxf(d4.x, d4.y), fmaxf(d4.z, d4.w)));
    }
    float mn = fminf(fminf(mn0, mn1), fminf(mn2, mn3));
    float mx = fmaxf(fmaxf(mx0, mx1), fmaxf(mx2, mx3));
    #pragma unroll
    for (int o = 16; o; o >>= 1) {
        mn = fminf(mn, __shfl_xor_sync(0xffffffffu, mn, o));
        mx = fmaxf(mx, __shfl_xor_sync(0xffffffffu, mx, o));
    }
    __shared__ float smn[8], smx[8];
    if ((threadIdx.x & 31) == 0) { smn[threadIdx.x >> 5] = mn; smx[threadIdx.x >> 5] = mx; }
    __syncthreads();
    if (threadIdx.x < 32) {
        mn = (threadIdx.x < 8) ? smn[threadIdx.x] : INFINITY;
        mx = (threadIdx.x < 8) ? smx[threadIdx.x] : -INFINITY;
        #pragma unroll
        for (int o = 4; o; o >>= 1) {
            mn = fminf(mn, __shfl_xor_sync(0xffffffffu, mn, o));
            mx = fmaxf(mx, __shfl_xor_sync(0xffffffffu, mx, o));
        }
        if (threadIdx.x == 0) {
            atomicMin(&g_mn[b], fenc(mn));
            atomicMax(&g_mx[b], fenc(mx));
        }
    }
}

// Fused kernel: float2 row-chunked ring (14 chunks x 2 rows), chunk-major,
// swizzle in the c-dimension (cc = (c+l)&31) so chunk offsets are immediates.
// Body n: P1(n) store 2 chunks; bar; P2(n) float2 prefix scans + prefetch; P3(n-1).
// Residues mod 14 in one barrier segment: writes {2n..2n+3}, P3 reads the other
// 10 residues {2n+4..2n+13} — exact disjoint partition.
__global__ void __launch_bounds__(512, 2) k_fused(
    const float* __restrict__ x,
    const float* __restrict__ gamma, const float* __restrict__ beta,
    const float* __restrict__ mmean, const float* __restrict__ mvar,
    float* __restrict__ out)
{
    extern __shared__ float2 Q2[];   // [chunk 14][l 32][cc 32]

    const int tid = threadIdx.x;
    const int c = tid & 31;        // channel (= lane)
    const int q = tid >> 5;        // w-output index within tile (= warp id)
    const int w0 = blockIdx.x * TW;
    const int h0 = blockIdx.y * CH;
    const int b  = blockIdx.z;

    const float mn  = fdec(g_mn[b]);
    const float inv = 1.0f / (fdec(g_mx[b]) - mn + EPSF);
    const float mni = mn * inv;

    const float sbn = gamma[c] * rsqrtf(mvar[c] + 1e-3f);
    const float bbn = fmaf(-mmean[c], sbn, beta[c]);

    for (int i = tid; i < NCHUNK * CHUNK2; i += 512) Q2[i] = make_float2(0.f, 0.f);

    // ---- addressing ----
    const int colA = w0 - 8 + q;       // l = q   (l==0 forced 0: exclusive base)
    const int colB = w0 + 8 + q;       // l = q + 16
    const bool okA = (q != 0) && ((unsigned)colA < (unsigned)W);
    const bool okB = ((unsigned)colB < (unsigned)W);
    const int offA = colA * C;
    const int offB = colB * C;
    const float* xb = x + (size_t)b * H * W * C + c;
    const int rs = W * C;              // 7168

    // float2-index within a chunk for (l, this thread's c), swizzled in c
    #define TB(l) ((l) * 32 + (((l) + c) & 31))
    const int b16p = TB(q + 16), b16m = TB(q);
    const int b8p  = TB(q + 12), b8m  = TB(q + 4);
    const int b4p  = TB(q + 10), b4m  = TB(q + 6);
    const int b2p  = TB(q + 9),  b2m  = TB(q + 7);
    #undef TB
    // P2 scan bases: lane c plays l; warp q owns channels q and q+16
    const int sc0 = c * 32 + ((c + q) & 31);
    const int sc1 = sc0 ^ 16;

    float* outP = out + ((long long)(b * H + h0 - 16) * W + (w0 + q)) * C + c;

    float pf0[4], pf1[4];
    #define PREFETCH(T0)                                                      \
        _Pragma("unroll")                                                     \
        for (int r4 = 0; r4 < 4; ++r4) {                                      \
            int a = h0 - 8 + (T0) + r4;                                       \
            float v0 = 0.0f, v1 = 0.0f;                                       \
            if ((unsigned)a < (unsigned)H) {                                  \
                const float* xr = xb + (long long)a * rs;                     \
                if (okA) v0 = fmaf(__ldg(xr + offA), inv, -mni);              \
                if (okB) v1 = fmaf(__ldg(xr + offB), inv, -mni);              \
            }                                                                 \
            pf0[r4] = v0; pf1[r4] = v1;                                       \
        }

    float V2 = 0.f, V4 = 0.f, V8 = 0.f, V16 = 0.f;
    int it = 0;

    PREFETCH(0);
    __syncthreads();                // ring zero-fill complete

    // Body with literal chunk base K2 = (2*it) % 14 (period 7 in it).
    #define BODY(K2)                                                          \
    if (it <= NSUP) {                                                         \
        if (it < NSUP) {                                                      \
            Q2[(K2) * CHUNK2 + b16m]       = make_float2(pf0[0], pf0[1]);     \
            Q2[((K2) + 1) * CHUNK2 + b16m] = make_float2(pf0[2], pf0[3]);     \
            Q2[(K2) * CHUNK2 + b16p]       = make_float2(pf1[0], pf1[1]);     \
            Q2[((K2) + 1) * CHUNK2 + b16p] = make_float2(pf1[2], pf1[3]);     \
        }                                                                     \
        __syncthreads();                                                      \
        if (it < NSUP) {                                                      \
            float2 v0  = Q2[(K2) * CHUNK2 + sc0];                             \
            float2 u0  = Q2[((K2) + 1) * CHUNK2 + sc0];                       \
            float2 v1  = Q2[(K2) * CHUNK2 + sc1];                             \
            float2 u1  = Q2[((K2) + 1) * CHUNK2 + sc1];                       \
            _Pragma("unroll")                                                 \
            for (int o = 1; o < 32; o <<= 1) {                                \
                float a0 = __shfl_up_sync(0xffffffffu, v0.x, o);              \
                float a1 = __shfl_up_sync(0xffffffffu, v0.y, o);              \
                float a2 = __shfl_up_sync(0xffffffffu, u0.x, o);              \
                float a3 = __shfl_up_sync(0xffffffffu, u0.y, o);              \
                float a4 = __shfl_up_sync(0xffffffffu, v1.x, o);              \
                float a5 = __shfl_up_sync(0xffffffffu, v1.y, o);              \
                float a6 = __shfl_up_sync(0xffffffffu, u1.x, o);              \
                float a7 = __shfl_up_sync(0xffffffffu, u1.y, o);              \
                if (c >= o) {                                                 \
                    v0.x += a0; v0.y += a1; u0.x += a2; u0.y += a3;           \
                    v1.x += a4; v1.y += a5; u1.x += a6; u1.y += a7;           \
                }                                                             \
            }                                                                 \
            Q2[(K2) * CHUNK2 + sc0]       = v0;                               \
            Q2[((K2) + 1) * CHUNK2 + sc0] = u0;                               \
            Q2[(K2) * CHUNK2 + sc1]       = v1;                               \
            Q2[((K2) + 1) * CHUNK2 + sc1] = u1;                               \
            if (it < NSUP - 1) { PREFETCH(4 * it + 4); }                      \
        }                                                                     \
        if (it >= 1) {                                                        \
            float* op = outP + (long long)(4 * (it - 1)) * rs;                \
            const bool emit = (it >= 5);                                      \
            const float2* QE16a = Q2 + ((((K2) + 12) % 14)) * CHUNK2;         \
            const float2* QE16b = Q2 + ((((K2) + 12) % 14) + 1) * CHUNK2;     \
            const float2* QL16a = Q2 + ((((K2) + 4) % 14)) * CHUNK2;          \
            const float2* QL16b = Q2 + ((((K2) + 4) % 14) + 1) * CHUNK2;      \
            const float2* QN2   = Q2 + ((((K2) + 10) % 14)) * CHUNK2;         \
            const float2* QE8b  = Q2 + ((((K2) + 10) % 14) + 1) * CHUNK2;     \
            const float2* QL8a  = Q2 + ((((K2) + 6) % 14)) * CHUNK2;          \
            const float2* QN5   = Q2 + ((((K2) + 6) % 14) + 1) * CHUNK2;      \
            const float2* QN4   = Q2 + ((((K2) + 8) % 14)) * CHUNK2;          \
            const float2* QN3   = Q2 + ((((K2) + 8) % 14) + 1) * CHUNK2;      \
            float2 Gp0 = QE16a[b16p], Gm0 = QE16a[b16m];                      \
            float2 Gp1 = QE16b[b16p], Gm1 = QE16b[b16m];                      \
            float2 Hp0 = QL16a[b16p], Hm0 = QL16a[b16m];                      \
            float2 Hp1 = QL16b[b16p], Hm1 = QL16b[b16m];                      \
            float2 Ip0 = QN2[b8p],  Im0 = QN2[b8m];                           \
            float2 Ip1 = QE8b[b8p], Im1 = QE8b[b8m];                          \
            float2 Jp0 = QL8a[b8p], Jm0 = QL8a[b8m];                          \
            float2 Jp1 = QN5[b8p],  Jm1 = QN5[b8m];                           \
            float2 A5p = QN5[b4p], A5m = QN5[b4m];                            \
            float2 A4p = QN4[b4p], A4m = QN4[b4m];                            \
            float2 A3p = QN3[b4p], A3m = QN3[b4m];                            \
            float2 A2p = QN2[b4p], A2m = QN2[b4m];                            \
            float2 B5p = QN5[b2p], B5m = QN5[b2m];                            \
            float2 B4p = QN4[b2p], B4m = QN4[b2m];                            \
            float2 B3p = QN3[b2p], B3m = QN3[b2m];                            \
            float2 B2p = QN2[b2p], B2m = QN2[b2m];                            \
            V16 += (Gp0.x - Gm0.x) - (Hp0.x - Hm0.x);                         \
            V8  += (Ip0.x - Im0.x) - (Jp0.x - Jm0.x);                         \
            V4  += (A3p.x - A3m.x) - (A5p.x - A5m.x);                         \
            V2  += (B4p.y - B4m.y) - (B5p.y - B5m.y);                         \
            if (emit) { EMIT(0) }                                             \
            V16 += (Gp0.y - Gm0.y) - (Hp0.y - Hm0.y);                         \
            V8  += (Ip0.y - Im0.y) - (Jp0.y - Jm0.y);                         \
            V4  += (A3p.y - A3m.y) - (A5p.y - A5m.y);                         \
            V2  += (B3p.x - B3m.x) - (B4p.x - B4m.x);                         \
            if (emit) { EMIT(1) }                                             \
            V16 += (Gp1.x - Gm1.x) - (Hp1.x - Hm1.x);                         \
            V8  += (Ip1.x - Im1.x) - (Jp1.x - Jm1.x);                         \
            V4  += (A2p.x - A2m.x) - (A4p.x - A4m.x);                         \
            V2  += (B3p.y - B3m.y) - (B4p.y - B4m.y);                         \
            if (emit) { EMIT(2) }                                             \
            V16 += (Gp1.y - Gm1.y) - (Hp1.y - Hm1.y);                         \
            V8  += (Ip1.y - Im1.y) - (Jp1.y - Jm1.y);                         \
            V4  += (A2p.y - A2m.y) - (A4p.y - A4m.y);                         \
            V2  += (B2p.x - B2m.x) - (B3p.x - B3m.x);                         \
            if (emit) { EMIT(3) }                                             \
        }                                                                     \
        ++it;                                                                 \
    }

    #define EMIT(R)                                                           \
        {                                                                     \
            float m2  = fmaxf(V2,  0.f) + EPSF;                               \
            float m4  = fmaxf(V4,  0.f) + EPSF;                               \
            float m8  = fmaxf(V8,  0.f) + EPSF;                               \
            float m16 = fmaxf(V16, 0.f) + EPSF;                               \
            float alpha = 0.1f * (__log2f(m16 * m16 * m16 * m8)               \
                                - __log2f(m2 * m2 * m2 * m4));                \
            op[(R) * rs] = fmaf(alpha, sbn, bbn);                             \
        }

    // 33 live bodies; chunk base has period 7 -> 5 groups x 7 literal bodies.
    #pragma unroll 1
    for (int grp = 0; grp < 5; ++grp) {
        BODY(0) BODY(2) BODY(4) BODY(6) BODY(8) BODY(10) BODY(12)
    }
    #undef EMIT
    #undef BODY
    #undef PREFETCH
}

extern "C" void kernel_launch(void* const* d_in, const int* in_sizes, int n_in,
                              void* d_out, int out_size) {
    const float* x     = (const float*)d_in[0];
    const float* gamma = (const float*)d_in[1];
    const float* beta  = (const float*)d_in[2];
    const float* mmean = (const float*)d_in[3];
    const float* mvar  = (const float*)d_in[4];
    float* out = (float*)d_out;

    cudaFuncSetAttribute(k_fused, cudaFuncAttributeMaxDynamicSharedMemorySize, QBYTES);

    dim3 g1(56, B);
    k1_minmax<<<g1, 256>>>((const float4*)x);
    dim3 gf(W / TW, H / CH, B);   // 14 x 2 x 16 = 448 blocks
    k_fused<<<gf, 512, QBYTES>>>(x, gamma, beta, mmean, mvar, out);
}

// round 16
// speedup vs baseline: 1.1666x; 1.1666x over previous
#include <cuda_runtime.h>
#include <math.h>

#define EPSF 1e-7f

static constexpr int B = 16, H = 224, W = 224, C = 32;
static constexpr int TW = 16;      // output columns per job
static constexpr int CHB = 120;    // rows per big job
static constexpr int CHS = 52;     // rows per small job (120 + 52 + 52 = 224)
static constexpr int QD = 28;      // ring depth: pipelined P3 span needs >= 28
static constexpr int QROW = 1024;  // floats per ring row: 32 l-entries x 32 c, XOR-swizzled
static constexpr int QBYTES = QD * QROW * 4;   // 114688 B -> 2 CTAs/SM
static constexpr int NBIG = 14 * B;            // 224 big jobs
static constexpr int NGRID = NBIG + 2 * NBIG;  // + 448 small jobs = 672 blocks

// Static init; atomicMin/Max accumulation is idempotent across graph replays.
__device__ unsigned g_mn[B] = {
    0xFFFFFFFFu, 0xFFFFFFFFu, 0xFFFFFFFFu, 0xFFFFFFFFu,
    0xFFFFFFFFu, 0xFFFFFFFFu, 0xFFFFFFFFu, 0xFFFFFFFFu,
    0xFFFFFFFFu, 0xFFFFFFFFu, 0xFFFFFFFFu, 0xFFFFFFFFu,
    0xFFFFFFFFu, 0xFFFFFFFFu, 0xFFFFFFFFu, 0xFFFFFFFFu};
__device__ unsigned g_mx[B] = {0};

// Monotonic unsigned encoding of float for atomicMin/Max
__device__ __forceinline__ unsigned fenc(float f) {
    unsigned u = __float_as_uint(f);
    return (u & 0x80000000u) ? ~u : (u | 0x80000000u);
}
__device__ __forceinline__ float fdec(unsigned u) {
    return __uint_as_float((u & 0x80000000u) ? (u ^ 0x80000000u) : ~u);
}

// K1: per-sample min/max. grid = (56, B), 256 threads, 4 independent accumulators (MLP=4).
__global__ void __launch_bounds__(256) k1_minmax(const float4* __restrict__ x) {
    int b = blockIdx.y;
    const int N4 = H * W * C / 4;              // 401408
    const int S  = 56 * 256;                   // 14336
    const float4* xb = x + (size_t)b * N4;
    int tid = blockIdx.x * 256 + threadIdx.x;
    float mn0 = INFINITY, mn1 = INFINITY, mn2 = INFINITY, mn3 = INFINITY;
    float mx0 = -INFINITY, mx1 = -INFINITY, mx2 = -INFINITY, mx3 = -INFINITY;
    #pragma unroll 1
    for (int i = tid; i < N4; i += 4 * S) {
        float4 a  = xb[i];
        float4 b4 = xb[i + S];
        float4 c4 = xb[i + 2 * S];
        float4 d4 = xb[i + 3 * S];
        mn0 = fminf(mn0, fminf(fminf(a.x, a.y), fminf(a.z, a.w)));
        mx0 = fmaxf(mx0, fmaxf(fmaxf(a.x, a.y), fmaxf(a.z, a.w)));
        mn1 = fminf(mn1, fminf(fminf(b4.x, b4.y), fminf(b4.z, b4.w)));
        mx1 = fmaxf(mx1, fmaxf(fmaxf(b4.x, b4.y), fmaxf(b4.z, b4.w)));
        mn2 = fminf(mn2, fminf(fminf(c4.x, c4.y), fminf(c4.z, c4.w)));
        mx2 = fmaxf(mx2, fmaxf(fmaxf(c4.x, c4.y), fmaxf(c4.z, c4.w)));
        mn3 = fminf(mn3, fminf(fminf(d4.x, d4.y), fminf(d4.z, d4.w)));
        mx3 = fmaxf(mx3, fmaxf(fmaxf(d4.x, d4.y), fmaxf(d4.z, d4.w)));
    }
    float mn = fminf(fminf(mn0, mn1), fminf(mn2, mn3));
    float mx = fmaxf(fmaxf(mx0, mx1), fmaxf(mx2, mx3));
    #pragma unroll
    for (int o = 16; o; o >>= 1) {
        mn = fminf(mn, __shfl_xor_sync(0xffffffffu, mn, o));
        mx = fmaxf(mx, __shfl_xor_sync(0xffffffffu, mx, o));
    }
    __shared__ float smn[8], smx[8];
    if ((threadIdx.x & 31) == 0) { smn[threadIdx.x >> 5] = mn; smx[threadIdx.x >> 5] = mx; }
    __syncthreads();
    if (threadIdx.x < 32) {
        mn = (threadIdx.x < 8) ? smn[threadIdx.x] : INFINITY;
        mx = (threadIdx.x < 8) ? smx[threadIdx.x] : -INFINITY;
        #pragma unroll
        for (int o = 4; o; o >>= 1) {
            mn = fminf(mn, __shfl_xor_sync(0xffffffffu, mn, o));
            mx = fmaxf(mx, __shfl_xor_sync(0xffffffffu, mx, o));
        }
        if (threadIdx.x == 0) {
            atomicMin(&g_mn[b], fenc(mn));
            atomicMax(&g_mx[b], fenc(mx));
        }
    }
}

// Fused kernel (R13 body, unchanged): single barrier per 4-row super-iteration,
// static ring slots via 7-periodic unroll. NEW: heterogeneous 1-D job grid —
// blocks 0..223 are big jobs (h0=0, 120 output rows), blocks 224..671 are small
// jobs (h0=120 or 172, 52 rows). Bigs dispatch first: slots pack to ~204
// row-units each (big+small or 3x small) instead of the 2x128 wave schedule.
__global__ void __launch_bounds__(512, 2) k_fused(
    const float* __restrict__ x,
    const float* __restrict__ gamma, const float* __restrict__ beta,
    const float* __restrict__ mmean, const float* __restrict__ mvar,
    float* __restrict__ out)
{
    extern __shared__ float Q[];   // [QD][32 l][32 c], word(l,c) = l*32 + ((l+c)&31)

    const int tid = threadIdx.x;
    const int c = tid & 31;        // channel (= lane)
    const int q = tid >> 5;        // w-output index within tile (= warp id)

    // ---- job decode ----
    int w0, h0, b, ns;
    {
        const int i = blockIdx.x;
        if (i < NBIG) {
            b  = i / 14;
            w0 = (i % 14) * TW;
            h0 = 0;
            ns = (CHB + 16) / 4;           // 34
        } else {
            const int j   = i - NBIG;
            const int col = j >> 1;
            b  = col / 14;
            w0 = (col % 14) * TW;
            h0 = CHB + (j & 1) * CHS;      // 120 or 172
            ns = (CHS + 16) / 4;           // 17
        }
    }

    const float mn  = fdec(g_mn[b]);
    const float inv = 1.0f / (fdec(g_mx[b]) - mn + EPSF);
    const float mni = mn * inv;

    const float sbn = gamma[c] * rsqrtf(mvar[c] + 1e-3f);
    const float bbn = fmaf(-mmean[c], sbn, beta[c]);

    // Pre-zero the ring: unwritten slots must read as 0 during warm-up.
    for (int i = tid; i < QD * QROW; i += 512) Q[i] = 0.0f;

    // ---- addressing ----
    const int colA = w0 - 8 + q;       // l = q      (l==0 forced 0: exclusive prefix base)
    const int colB = w0 + 8 + q;       // l = q + 16
    const bool okA = (q != 0) && ((unsigned)colA < (unsigned)W);
    const bool okB = ((unsigned)colB < (unsigned)W);
    const int offA = colA * C;
    const int offB = colB * C;
    const float* xb = x + (size_t)b * H * W * C + c;
    const int rs = W * C;              // 7168

    // swizzled word offsets (lw = q + 8 is the output column's l-position)
    #define SWZ(l) ((l) * 32 + (((l) + c) & 31))
    const int wA   = SWZ(q);           // == l = lw - 8
    const int wB   = SWZ(q + 16);      // == l = lw + 8
    const int o8p  = SWZ(q + 12), o8m = SWZ(q + 4);
    const int o4p  = SWZ(q + 10), o4m = SWZ(q + 6);
    const int o2p  = SWZ(q + 9),  o2m = SWZ(q + 7);
    #undef SWZ
    // P2 in-place scan words (lane c plays role of l), loop-invariant
    const int wd0 = c * 32 + ((c + q) & 31);
    const int wd1 = c * 32 + ((c + q + 16) & 31);

    // output base pointer at t=0 (h = h0 + t - 16); only dereferenced for t>=16.
    float* outP = out + ((long long)(b * H + h0 - 16) * W + (w0 + q)) * C + c;

    // ---- register prefetch: 4 rows x 2 values (one super-iteration of lead) ----
    float pf0[4], pf1[4];
    #define PREFETCH(T0)                                                      \
        _Pragma("unroll")                                                     \
        for (int r4 = 0; r4 < 4; ++r4) {                                      \
            int a = h0 - 8 + (T0) + r4;                                       \
            float v0 = 0.0f, v1 = 0.0f;                                       \
            if ((unsigned)a < (unsigned)H) {                                  \
                const float* xr = xb + (long long)a * rs;                     \
                if (okA) v0 = fmaf(__ldg(xr + offA), inv, -mni);              \
                if (okB) v1 = fmaf(__ldg(xr + offB), inv, -mni);              \
            }                                                                 \
            pf0[r4] = v0; pf1[r4] = v1;                                       \
        }

    float V2 = 0.f, V4 = 0.f, V8 = 0.f, V16 = 0.f;
    int it = 0;

    PREFETCH(0);
    __syncthreads();                // ring zero-fill complete

    // One pipeline body with compile-time slot base S = (4*it) % 28.
    // Safety (QD=28): P3(n-1) reads slots {s+8..s+27}; P1(n+1) writes {s+4..s+7};
    // P2(n) writes {s..s+3} — pairwise disjoint mod 28; one barrier per body.
    #define BODY(S)                                                           \
    if (it <= ns) {                                                           \
        if (it < ns) {                                                        \
            /* P1: store 4 prefetched raw rows into slots S..S+3 (static) */  \
            _Pragma("unroll")                                                 \
            for (int r = 0; r < 4; ++r) {                                     \
                float* Qs = Q + ((S) + r) * QROW;                             \
                Qs[wA] = pf0[r];                                              \
                Qs[wB] = pf1[r];                                              \
            }                                                                 \
        }                                                                     \
        __syncthreads();                                                      \
        if (it < ns) {                                                        \
            /* P2: in-place inclusive prefix along l; 8 independent chains */ \
            _Pragma("unroll")                                                 \
            for (int r = 0; r < 4; ++r) {                                     \
                float* Qs = Q + ((S) + r) * QROW;                             \
                float v0s = Qs[wd0];                                          \
                float v1s = Qs[wd1];                                          \
                _Pragma("unroll")                                             \
                for (int o = 1; o < 32; o <<= 1) {                            \
                    float n0 = __shfl_up_sync(0xffffffffu, v0s, o);           \
                    float n1 = __shfl_up_sync(0xffffffffu, v1s, o);           \
                    if (c >= o) { v0s += n0; v1s += n1; }                     \
                }                                                             \
                Qs[wd0] = v0s;                                                \
                Qs[wd1] = v1s;                                                \
            }                                                                 \
            if (it < ns - 1) { PREFETCH(4 * it + 4); }                        \
        }                                                                     \
        if (it >= 1) {                                                        \
            /* P3(it-1): slots (S+24)%28 .. +3, all offsets static */         \
            const int tp0 = 4 * (it - 1);                                     \
            float* op = outP + (long long)tp0 * rs;                           \
            const bool emit = (it >= 5);                                      \
            _Pragma("unroll")                                                 \
            for (int r = 0; r < 4; ++r) {                                     \
                const int U   = ((S) + 24) % 28 + r;   /* <= 27, no wrap */   \
                const float* r0  = Q + U * QROW;                              \
                const float* r4  = Q + ((U + 24) % 28) * QROW;                \
                const float* r6  = Q + ((U + 22) % 28) * QROW;                \
                const float* r7  = Q + ((U + 21) % 28) * QROW;                \
                const float* r9  = Q + ((U + 19) % 28) * QROW;                \
                const float* r10 = Q + ((U + 18) % 28) * QROW;                \
                const float* r12 = Q + ((U + 16) % 28) * QROW;                \
                const float* r16 = Q + ((U + 12) % 28) * QROW;                \
                V16 += (r0 [wB]  - r0 [wA])  - (r16[wB]  - r16[wA]);          \
                V8  += (r4 [o8p] - r4 [o8m]) - (r12[o8p] - r12[o8m]);         \
                V4  += (r6 [o4p] - r6 [o4m]) - (r10[o4p] - r10[o4m]);         \
                V2  += (r7 [o2p] - r7 [o2m]) - (r9 [o2p] - r9 [o2m]);         \
                if (emit) {                                                   \
                    float m2  = fmaxf(V2,  0.f) + EPSF;                       \
                    float m4  = fmaxf(V4,  0.f) + EPSF;                       \
                    float m8  = fmaxf(V8,  0.f) + EPSF;                       \
                    float m16 = fmaxf(V16, 0.f) + EPSF;                       \
                    float alpha = 0.1f * (__log2f(m16 * m16 * m16 * m8)       \
                                        - __log2f(m2 * m2 * m2 * m4));        \
                    op[r * rs] = fmaf(alpha, sbn, bbn);                       \
                }                                                             \
            }                                                                 \
        }                                                                     \
        ++it;                                                                 \
    }

    // 35 static bodies (big jobs use all 35; small jobs exit via the it guard).
    #pragma unroll 1
    for (int grp = 0; grp < 5; ++grp) {
        BODY(0) BODY(4) BODY(8) BODY(12) BODY(16) BODY(20) BODY(24)
    }
    #undef BODY
    #undef PREFETCH
}

extern "C" void kernel_launch(void* const* d_in, const int* in_sizes, int n_in,
                              void* d_out, int out_size) {
    const float* x     = (const float*)d_in[0];
    const float* gamma = (const float*)d_in[1];
    const float* beta  = (const float*)d_in[2];
    const float* mmean = (const float*)d_in[3];
    const float* mvar  = (const float*)d_in[4];
    float* out = (float*)d_out;

    cudaFuncSetAttribute(k_fused, cudaFuncAttributeMaxDynamicSharedMemorySize, QBYTES);

    dim3 g1(56, B);
    k1_minmax<<<g1, 256>>>((const float4*)x);
    k_fused<<<NGRID, 512, QBYTES>>>(x, gamma, beta, mmean, mvar, out);
}

// round 17
// speedup vs baseline: 1.2009x; 1.0294x over previous
#include <cuda_runtime.h>
#include <math.h>

#define EPSF 1e-7f

static constexpr int B = 16, H = 224, W = 224, C = 32;
static constexpr int TW = 16;      // output columns per job
static constexpr int CHB = 120;    // rows per big job
static constexpr int CHS = 52;     // rows per small job (120 + 52 + 52 = 224)
static constexpr int QD = 28;      // ring depth: pipelined P3 span needs >= 28
static constexpr int QROW = 1024;  // floats per ring row: 32 l-entries x 32 c, XOR-swizzled
static constexpr int QBYTES = QD * QROW * 4;   // 114688 B -> 2 CTAs/SM
static constexpr int NBIG = 14 * B;            // 224 big jobs
static constexpr int NGRID = NBIG + 2 * NBIG;  // + 448 small jobs = 672 blocks

// Static init; atomicMin/Max accumulation is idempotent across graph replays.
__device__ unsigned g_mn[B] = {
    0xFFFFFFFFu, 0xFFFFFFFFu, 0xFFFFFFFFu, 0xFFFFFFFFu,
    0xFFFFFFFFu, 0xFFFFFFFFu, 0xFFFFFFFFu, 0xFFFFFFFFu,
    0xFFFFFFFFu, 0xFFFFFFFFu, 0xFFFFFFFFu, 0xFFFFFFFFu,
    0xFFFFFFFFu, 0xFFFFFFFFu, 0xFFFFFFFFu, 0xFFFFFFFFu};
__device__ unsigned g_mx[B] = {0};

// Monotonic unsigned encoding of float for atomicMin/Max
__device__ __forceinline__ unsigned fenc(float f) {
    unsigned u = __float_as_uint(f);
    return (u & 0x80000000u) ? ~u : (u | 0x80000000u);
}
__device__ __forceinline__ float fdec(unsigned u) {
    return __uint_as_float((u & 0x80000000u) ? (u ^ 0x80000000u) : ~u);
}

// K1: per-sample min/max. grid = (56, B), 256 threads, 4 independent accumulators (MLP=4).
__global__ void __launch_bounds__(256) k1_minmax(const float4* __restrict__ x) {
    int b = blockIdx.y;
    const int N4 = H * W * C / 4;              // 401408
    const int S  = 56 * 256;                   // 14336
    const float4* xb = x + (size_t)b * N4;
    int tid = blockIdx.x * 256 + threadIdx.x;
    float mn0 = INFINITY, mn1 = INFINITY, mn2 = INFINITY, mn3 = INFINITY;
    float mx0 = -INFINITY, mx1 = -INFINITY, mx2 = -INFINITY, mx3 = -INFINITY;
    #pragma unroll 1
    for (int i = tid; i < N4; i += 4 * S) {
        float4 a  = xb[i];
        float4 b4 = xb[i + S];
        float4 c4 = xb[i + 2 * S];
        float4 d4 = xb[i + 3 * S];
        mn0 = fminf(mn0, fminf(fminf(a.x, a.y), fminf(a.z, a.w)));
        mx0 = fmaxf(mx0, fmaxf(fmaxf(a.x, a.y), fmaxf(a.z, a.w)));
        mn1 = fminf(mn1, fminf(fminf(b4.x, b4.y), fminf(b4.z, b4.w)));
        mx1 = fmaxf(mx1, fmaxf(fmaxf(b4.x, b4.y), fmaxf(b4.z, b4.w)));
        mn2 = fminf(mn2, fminf(fminf(c4.x, c4.y), fminf(c4.z, c4.w)));
        mx2 = fmaxf(mx2, fmaxf(fmaxf(c4.x, c4.y), fmaxf(c4.z, c4.w)));
        mn3 = fminf(mn3, fminf(fminf(d4.x, d4.y), fminf(d4.z, d4.w)));
        mx3 = fmaxf(mx3, fmaxf(fmaxf(d4.x, d4.y), fmaxf(d4.z, d4.w)));
    }
    float mn = fminf(fminf(mn0, mn1), fminf(mn2, mn3));
    float mx = fmaxf(fmaxf(mx0, mx1), fmaxf(mx2, mx3));
    #pragma unroll
    for (int o = 16; o; o >>= 1) {
        mn = fminf(mn, __shfl_xor_sync(0xffffffffu, mn, o));
        mx = fmaxf(mx, __shfl_xor_sync(0xffffffffu, mx, o));
    }
    __shared__ float smn[8], smx[8];
    if ((threadIdx.x & 31) == 0) { smn[threadIdx.x >> 5] = mn; smx[threadIdx.x >> 5] = mx; }
    __syncthreads();
    if (threadIdx.x < 32) {
        mn = (threadIdx.x < 8) ? smn[threadIdx.x] : INFINITY;
        mx = (threadIdx.x < 8) ? smx[threadIdx.x] : -INFINITY;
        #pragma unroll
        for (int o = 4; o; o >>= 1) {
            mn = fminf(mn, __shfl_xor_sync(0xffffffffu, mn, o));
            mx = fmaxf(mx, __shfl_xor_sync(0xffffffffu, mx, o));
        }
        if (threadIdx.x == 0) {
            atomicMin(&g_mn[b], fenc(mn));
            atomicMax(&g_mx[b], fenc(mx));
        }
    }
}

// Fused kernel: R16 structure (heterogeneous job grid, single barrier per body,
// static ring slots) + P3 temporal tap-sharing: leave diffs for scales 2 and 4
// equal enter diffs computed 2/4 rows earlier -> carried in 6 registers, deleting
// the r9/r10 slot loads (P3: 64 -> 48 LDS per warp-body). Bit-identical values.
__global__ void __launch_bounds__(512, 2) k_fused(
    const float* __restrict__ x,
    const float* __restrict__ gamma, const float* __restrict__ beta,
    const float* __restrict__ mmean, const float* __restrict__ mvar,
    float* __restrict__ out)
{
    extern __shared__ float Q[];   // [QD][32 l][32 c], word(l,c) = l*32 + ((l+c)&31)

    const int tid = threadIdx.x;
    const int c = tid & 31;        // channel (= lane)
    const int q = tid >> 5;        // w-output index within tile (= warp id)

    // ---- job decode ----
    int w0, h0, b, ns;
    {
        const int i = blockIdx.x;
        if (i < NBIG) {
            b  = i / 14;
            w0 = (i % 14) * TW;
            h0 = 0;
            ns = (CHB + 16) / 4;           // 34
        } else {
            const int j   = i - NBIG;
            const int col = j >> 1;
            b  = col / 14;
            w0 = (col % 14) * TW;
            h0 = CHB + (j & 1) * CHS;      // 120 or 172
            ns = (CHS + 16) / 4;           // 17
        }
    }

    const float mn  = fdec(g_mn[b]);
    const float inv = 1.0f / (fdec(g_mx[b]) - mn + EPSF);
    const float mni = mn * inv;

    const float sbn = gamma[c] * rsqrtf(mvar[c] + 1e-3f);
    const float bbn = fmaf(-mmean[c], sbn, beta[c]);

    // Pre-zero the ring: unwritten slots must read as 0 during warm-up.
    for (int i = tid; i < QD * QROW; i += 512) Q[i] = 0.0f;

    // ---- addressing ----
    const int colA = w0 - 8 + q;       // l = q      (l==0 forced 0: exclusive prefix base)
    const int colB = w0 + 8 + q;       // l = q + 16
    const bool okA = (q != 0) && ((unsigned)colA < (unsigned)W);
    const bool okB = ((unsigned)colB < (unsigned)W);
    const int offA = colA * C;
    const int offB = colB * C;
    const float* xb = x + (size_t)b * H * W * C + c;
    const int rs = W * C;              // 7168

    // swizzled word offsets (lw = q + 8 is the output column's l-position)
    #define SWZ(l) ((l) * 32 + (((l) + c) & 31))
    const int wA   = SWZ(q);           // == l = lw - 8
    const int wB   = SWZ(q + 16);      // == l = lw + 8
    const int o8p  = SWZ(q + 12), o8m = SWZ(q + 4);
    const int o4p  = SWZ(q + 10), o4m = SWZ(q + 6);
    const int o2p  = SWZ(q + 9),  o2m = SWZ(q + 7);
    #undef SWZ
    // P2 in-place scan words (lane c plays role of l), loop-invariant
    const int wd0 = c * 32 + ((c + q) & 31);
    const int wd1 = c * 32 + ((c + q + 16) & 31);

    // output base pointer at t=0 (h = h0 + t - 16); only dereferenced for t>=16.
    float* outP = out + ((long long)(b * H + h0 - 16) * W + (w0 + q)) * C + c;

    // ---- register prefetch: 4 rows x 2 values (one super-iteration of lead) ----
    float pf0[4], pf1[4];
    #define PREFETCH(T0)                                                      \
        _Pragma("unroll")                                                     \
        for (int r4 = 0; r4 < 4; ++r4) {                                      \
            int a = h0 - 8 + (T0) + r4;                                       \
            float v0 = 0.0f, v1 = 0.0f;                                       \
            if ((unsigned)a < (unsigned)H) {                                  \
                const float* xr = xb + (long long)a * rs;                     \
                if (okA) v0 = fmaf(__ldg(xr + offA), inv, -mni);              \
                if (okB) v1 = fmaf(__ldg(xr + offB), inv, -mni);              \
            }                                                                 \
            pf0[r4] = v0; pf1[r4] = v1;                                       \
        }

    float V2 = 0.f, V4 = 0.f, V8 = 0.f, V16 = 0.f;
    // carried leave diffs: scale-2 (distance 2 rows) and scale-4 (distance 4 rows).
    // Init 0 == the zero-filled slots the deleted loads would have read.
    float c2a = 0.f, c2b = 0.f;
    float c4a = 0.f, c4b = 0.f, c4c = 0.f, c4d = 0.f;
    int it = 0;

    PREFETCH(0);
    __syncthreads();                // ring zero-fill complete

    // One pipeline body with compile-time slot base S = (4*it) % 28.
    // Safety (QD=28): P3(n-1) reads slots {s+8..s+27}; P1(n+1) writes {s+4..s+7};
    // P2(n) writes {s..s+3} — pairwise disjoint mod 28; one barrier per body.
    #define BODY(S)                                                           \
    if (it <= ns) {                                                           \
        if (it < ns) {                                                        \
            /* P1: store 4 prefetched raw rows into slots S..S+3 (static) */  \
            _Pragma("unroll")                                                 \
            for (int r = 0; r < 4; ++r) {                                     \
                float* Qs = Q + ((S) + r) * QROW;                             \
                Qs[wA] = pf0[r];                                              \
                Qs[wB] = pf1[r];                                              \
            }                                                                 \
        }                                                                     \
        __syncthreads();                                                      \
        if (it < ns) {                                                        \
            /* P2: in-place inclusive prefix along l; 8 independent chains */ \
            _Pragma("unroll")                                                 \
            for (int r = 0; r < 4; ++r) {                                     \
                float* Qs = Q + ((S) + r) * QROW;                             \
                float v0s = Qs[wd0];                                          \
                float v1s = Qs[wd1];                                          \
                _Pragma("unroll")                                             \
                for (int o = 1; o < 32; o <<= 1) {                            \
                    float n0 = __shfl_up_sync(0xffffffffu, v0s, o);           \
                    float n1 = __shfl_up_sync(0xffffffffu, v1s, o);           \
                    if (c >= o) { v0s += n0; v1s += n1; }                     \
                }                                                             \
                Qs[wd0] = v0s;                                                \
                Qs[wd1] = v1s;                                                \
            }                                                                 \
            if (it < ns - 1) { PREFETCH(4 * it + 4); }                        \
        }                                                                     \
        if (it >= 1) {                                                        \
            /* P3(it-1): static slots; scale-2/4 leave diffs come from carry */\
            const int tp0 = 4 * (it - 1);                                     \
            float* op = outP + (long long)tp0 * rs;                           \
            const bool emit = (it >= 5);                                      \
            float d2n[4], d4n[4];                                             \
            _Pragma("unroll")                                                 \
            for (int r = 0; r < 4; ++r) {                                     \
                const int U   = ((S) + 24) % 28 + r;   /* <= 27, no wrap */   \
                const float* r0  = Q + U * QROW;                              \
                const float* r4  = Q + ((U + 24) % 28) * QROW;                \
                const float* r6  = Q + ((U + 22) % 28) * QROW;                \
                const float* r7  = Q + ((U + 21) % 28) * QROW;                \
                const float* r12 = Q + ((U + 16) % 28) * QROW;                \
                const float* r16 = Q + ((U + 12) % 28) * QROW;                \
                d4n[r] = r6[o4p] - r6[o4m];                                   \
                d2n[r] = r7[o2p] - r7[o2m];                                   \
                V16 += (r0 [wB]  - r0 [wA])  - (r16[wB]  - r16[wA]);          \
                V8  += (r4 [o8p] - r4 [o8m]) - (r12[o8p] - r12[o8m]);         \
                V4  += d4n[r] - ((r == 0) ? c4a : (r == 1) ? c4b               \
                                : (r == 2) ? c4c : c4d);                      \
                V2  += d2n[r] - ((r == 0) ? c2a : (r == 1) ? c2b               \
                                : d2n[r - 2]);                                \
                if (emit) {                                                   \
                    float m2  = fmaxf(V2,  0.f) + EPSF;                       \
                    float m4  = fmaxf(V4,  0.f) + EPSF;                       \
                    float m8  = fmaxf(V8,  0.f) + EPSF;                       \
                    float m16 = fmaxf(V16, 0.f) + EPSF;                       \
                    float alpha = 0.1f * (__log2f(m16 * m16 * m16 * m8)       \
                                        - __log2f(m2 * m2 * m2 * m4));        \
                    op[r * rs] = fmaf(alpha, sbn, bbn);                       \
                }                                                             \
            }                                                                 \
            c4a = d4n[0]; c4b = d4n[1]; c4c = d4n[2]; c4d = d4n[3];           \
            c2a = d2n[2]; c2b = d2n[3];                                       \
        }                                                                     \
        ++it;                                                                 \
    }

    // 35 static bodies (big jobs use all 35; small jobs exit via the it guard).
    #pragma unroll 1
    for (int grp = 0; grp < 5; ++grp) {
        BODY(0) BODY(4) BODY(8) BODY(12) BODY(16) BODY(20) BODY(24)
    }
    #undef BODY
    #undef PREFETCH
}

extern "C" void kernel_launch(void* const* d_in, const int* in_sizes, int n_in,
                              void* d_out, int out_size) {
    const float* x     = (const float*)d_in[0];
    const float* gamma = (const float*)d_in[1];
    const float* beta  = (const float*)d_in[2];
    const float* mmean = (const float*)d_in[3];
    const float* mvar  = (const float*)d_in[4];
    float* out = (float*)d_out;

    cudaFuncSetAttribute(k_fused, cudaFuncAttributeMaxDynamicSharedMemorySize, QBYTES);

    dim3 g1(56, B);
    k1_minmax<<<g1, 256>>>((const float4*)x);
    k_fused<<<NGRID, 512, QBYTES>>>(x, gamma, beta, mmean, mvar, out);
}